// round 7
// baseline (speedup 1.0000x reference)
#include <cuda_runtime.h>
#include <cuda_fp16.h>
#include <cstdint>

#define I_DIM   128
#define O_DIM   128
#define G_NUM   128
#define G1      129
#define B_DIM   8192
#define C_CHUNKS 4
#define ICHUNK  (I_DIM / C_CHUNKS)   /* 32 */
#define BT      256
#define NBT     (B_DIM / BT)         /* 32 */
#define THREADS 512
#define SLB     (G1 * 128)           /* 16512 B: one half-slice (129 rows x 128B) */
#define SLB_U4  (SLB / 16)           /* 1032 uint4 per slice */
#define NBUF    4

// dynamic smem layout for main kernel
#define OFF_BUF   0                              /* 4 x SLB = 66048 */
#define OFF_GD    (NBUF * SLB)                   /* 32 KB descriptors */
#define OFF_SB    (OFF_GD + ICHUNK * BT * 4)     /* 98816 */
#define OFF_SIL   (OFF_SB + 132 * 4)             /* 99344 */
#define SMEM_MAIN (OFF_SIL + 128 * 4 + 16)       /* 99872 */

// Static device scratch (allocation-free per harness rules)
__device__ __align__(16) __half g_P2lo[(size_t)I_DIM * G1 * 64];  // [i][g][o<64]
__device__ __align__(16) __half g_P2hi[(size_t)I_DIM * G1 * 64];  // [i][g][o>=64]
__device__ float g_partial[C_CHUNKS][B_DIM][O_DIM];               // [c][b][o]

// ---------------------------------------------------------------------------
__device__ __forceinline__ void cp16(unsigned dst_smem, const void* src) {
    asm volatile("cp.async.cg.shared.global [%0], [%1], 16;"
                 :: "r"(dst_smem), "l"(src) : "memory");
}
__device__ __forceinline__ void cp_commit() {
    asm volatile("cp.async.commit_group;" ::: "memory");
}
template <int N>
__device__ __forceinline__ void cp_wait() {
    asm volatile("cp.async.wait_group %0;" :: "n"(N) : "memory");
}

// ---------------------------------------------------------------------------
// Kernel 1: transpose+quantize P[g][o][i] -> split lo/hi fp16 tables.
// PROVEN round-4 structure: block = (one g, 32 i's), 128 threads.
// tile[o][i_local] with i_local < 32 (second dim 33: in bounds, conflict-free).
// Only the final store differs: route o<64 to g_P2lo, o>=64 to g_P2hi.
// ---------------------------------------------------------------------------
__global__ void transpose_kernel(const float* __restrict__ P) {
    __shared__ float tile[O_DIM][33];
    const int g  = blockIdx.y;           // 0..128
    const int i0 = blockIdx.x * 32;      // 0..96
    const int t = threadIdx.x, w = t >> 5, lane = t & 31;
    const int quad = lane >> 3;          // 0..3
    const int sub  = lane & 7;           // 0..7

    const float4* src = (const float4*)(P + (size_t)g * O_DIM * I_DIM + i0);
    float4 v[8];
#pragma unroll
    for (int r = 0; r < 8; r++) {
        int o = w * 32 + r * 4 + quad;
        v[r] = src[(size_t)o * (I_DIM / 4) + sub];
    }
#pragma unroll
    for (int r = 0; r < 8; r++) {
        int o = w * 32 + r * 4 + quad;
        tile[o][sub * 4 + 0] = v[r].x;
        tile[o][sub * 4 + 1] = v[r].y;
        tile[o][sub * 4 + 2] = v[r].z;
        tile[o][sub * 4 + 3] = v[r].w;
    }
    __syncthreads();

    const int op = t & 63;          // o-pair index 0..63 (o = 2*op, 2*op+1)
    const int il = t >> 6;          // 0..1
    const int hf  = op >> 5;        // 0: o<64 -> lo table, 1: o>=64 -> hi
    const int op2 = op & 31;        // half2 index within 64-o half
    __half2* dst = hf ? (__half2*)g_P2hi : (__half2*)g_P2lo;
#pragma unroll
    for (int r = 0; r < 16; r++) {
        int i = il + 2 * r;         // 0..31 (in tile bounds)
        dst[((size_t)(i0 + i) * G1 + g) * 32 + op2] =
            __floats2half2_rn(tile[2 * op][i], tile[2 * op + 1][i]);
    }
}

// ---------------------------------------------------------------------------
// Kernel 2: gather + lerp. Block = 256 b x 32 i. Even warps gather lower-o
// halves from a 4-deep smem ring (cp.async.cg: L2->SMEM, bypasses L1); odd
// warps gather upper-o halves via LDG/L1. Two pipes in parallel.
// ---------------------------------------------------------------------------
__global__ __launch_bounds__(THREADS, 1)
void main_kernel(const float* __restrict__ x,
                 const float* __restrict__ borders,
                 const float* __restrict__ invl) {
    extern __shared__ __align__(16) char smem[];
    unsigned* s_gd = (unsigned*)(smem + OFF_GD);      // [ICHUNK][BT]
    float*    s_b  = (float*)(smem + OFF_SB);
    float*    s_il = (float*)(smem + OFF_SIL);
    const unsigned bufS = (unsigned)__cvta_generic_to_shared(smem + OFF_BUF);

    const int t     = threadIdx.x;
    const int btile = blockIdx.x;    // 0..31
    const int chunk = blockIdx.y;    // 0..3
    const int b0    = btile * BT;
    const int i0    = chunk * ICHUNK;

    if (t < G1)    s_b[t]  = borders[t];
    if (t < G_NUM) s_il[t] = invl[t];

    // Prologue: prefetch lo-halves of slices i0..i0+2 into ring bufs 0..2.
    const char* loBase = (const char*)g_P2lo + (size_t)i0 * SLB;
#pragma unroll
    for (int s = 0; s < 3; s++) {
        for (int k = t; k < SLB_U4; k += THREADS)
            cp16(bufS + s * SLB + k * 16, loBase + (size_t)s * SLB + k * 16);
        cp_commit();
    }
    __syncthreads();   // s_b/s_il visible

    // Phase 1: bucket index g + weight d, packed (g | half(d)<<16)
    {
        const int bl    = t & (BT - 1);
        const int ibase = t >> 8;
#pragma unroll
        for (int p = 0; p < ICHUNK / 2; p++) {
            int il = ibase + 2 * p;
            float xv = x[(size_t)(i0 + il) * B_DIM + b0 + bl];
            float e  = __expf(-fabsf(xv));
            float cdf = (xv > 0.f) ? (1.f - 0.5f * e) : (0.5f * e);
            int g = (int)(cdf * (float)G_NUM);
            g = min(max(g, 0), G_NUM - 1);
            float d = (xv - s_b[g]) * s_il[g];
            unsigned db = (unsigned)__half_as_ushort(__float2half_rn(d));
            s_gd[il * BT + bl] = (unsigned)g | (db << 16);
        }
    }
    __syncthreads();

    const int w    = t >> 5;
    const int lane = t & 31;
    const int role = w & 1;          // 0: smem/lower-o, 1: L1/upper-o
    const int wb   = (w >> 1) * 32;  // 32 batch columns per warp pair
    const int lq   = lane >> 3;      // batch col within quad
    const int le   = lane & 7;       // 16B chunk within 128B half-row

    const __half2 one2 = __floats2half2_rn(1.f, 1.f);
    const __half2 z2   = __floats2half2_rn(0.f, 0.f);

    float4 accA[8], accB[8];
#pragma unroll
    for (int q = 0; q < 8; q++) {
        accA[q] = make_float4(0.f, 0.f, 0.f, 0.f);
        accB[q] = make_float4(0.f, 0.f, 0.f, 0.f);
    }

    for (int iiB = 0; iiB < ICHUNK; iiB += 4) {
        __half2 h0[8], h1[8], h2[8], h3[8];
#pragma unroll
        for (int q = 0; q < 8; q++) { h0[q] = z2; h1[q] = z2; h2[q] = z2; h3[q] = z2; }

#pragma unroll
        for (int u = 0; u < 4; u++) {
            const int ii = iiB + u;
            // Retire oldest group -> slice ii resident in buf[ii&3].
            cp_wait<2>();
            __syncthreads();   // all warps see slice ii; all done with buf[(ii-1)&3]

            // Refill: slice ii+3 into buf[(ii+3)&3] (== buf[(ii-1)&3], free now).
            if (ii + 3 < ICHUNK) {
                const char* src = (const char*)g_P2lo + (size_t)(i0 + ii + 3) * SLB;
                unsigned dst = bufS + ((ii + 3) & 3) * SLB;
                for (int k = t; k < SLB_U4; k += THREADS)
                    cp16(dst + k * 16, src + k * 16);
            }
            cp_commit();   // unconditional: keeps group bookkeeping uniform

            if (role == 0) {
                const uint4* lo4 = (const uint4*)(smem + OFF_BUF + (ii & 3) * SLB);
#pragma unroll
                for (int q = 0; q < 8; q++) {
                    unsigned v  = s_gd[ii * BT + wb + 4 * q + lq];
                    unsigned gi = v & 0xFFu;
                    unsigned dd = __byte_perm(v, v, 0x3232);
                    __half2 d2  = *(__half2*)&dd;
                    __half2 w2  = __hsub2(one2, d2);
                    uint4 A  = lo4[gi * 8 + le];        // row g   (LDS.128)
                    uint4 Bv = lo4[gi * 8 + 8 + le];    // row g+1
                    h0[q] = __hfma2(d2, *(__half2*)&Bv.x, __hfma2(w2, *(__half2*)&A.x, h0[q]));
                    h1[q] = __hfma2(d2, *(__half2*)&Bv.y, __hfma2(w2, *(__half2*)&A.y, h1[q]));
                    h2[q] = __hfma2(d2, *(__half2*)&Bv.z, __hfma2(w2, *(__half2*)&A.z, h2[q]));
                    h3[q] = __hfma2(d2, *(__half2*)&Bv.w, __hfma2(w2, *(__half2*)&A.w, h3[q]));
                }
            } else {
                const uint4* hi4 = (const uint4*)g_P2hi + (size_t)(i0 + ii) * (G1 * 8);
#pragma unroll
                for (int q = 0; q < 8; q++) {
                    unsigned v  = s_gd[ii * BT + wb + 4 * q + lq];
                    unsigned gi = v & 0xFFu;
                    unsigned dd = __byte_perm(v, v, 0x3232);
                    __half2 d2  = *(__half2*)&dd;
                    __half2 w2  = __hsub2(one2, d2);
                    uint4 A  = __ldg(hi4 + gi * 8 + le);      // row g   (LDG.128/L1)
                    uint4 Bv = __ldg(hi4 + gi * 8 + 8 + le);  // row g+1
                    h0[q] = __hfma2(d2, *(__half2*)&Bv.x, __hfma2(w2, *(__half2*)&A.x, h0[q]));
                    h1[q] = __hfma2(d2, *(__half2*)&Bv.y, __hfma2(w2, *(__half2*)&A.y, h1[q]));
                    h2[q] = __hfma2(d2, *(__half2*)&Bv.z, __hfma2(w2, *(__half2*)&A.z, h2[q]));
                    h3[q] = __hfma2(d2, *(__half2*)&Bv.w, __hfma2(w2, *(__half2*)&A.w, h3[q]));
                }
            }
        }

        // flush half2 partials into fp32 accumulators every 4 slices
#pragma unroll
        for (int q = 0; q < 8; q++) {
            float2 p0 = __half22float2(h0[q]);
            float2 p1 = __half22float2(h1[q]);
            float2 p2 = __half22float2(h2[q]);
            float2 p3 = __half22float2(h3[q]);
            accA[q].x += p0.x; accA[q].y += p0.y;
            accA[q].z += p1.x; accA[q].w += p1.y;
            accB[q].x += p2.x; accB[q].y += p2.y;
            accB[q].z += p3.x; accB[q].w += p3.y;
        }
    }

    // Store: lane covers o = role*64 + le*8 .. +7 for b = wb + 4q + lq.
#pragma unroll
    for (int q = 0; q < 8; q++) {
        int b = b0 + wb + 4 * q + lq;
        float4* dst = (float4*)&g_partial[chunk][b][role * 64 + le * 8];
        dst[0] = accA[q];
        dst[1] = accB[q];
    }
}

// ---------------------------------------------------------------------------
// Kernel 3: sum the C partials and transpose [b][o] -> out[o][b].
// ---------------------------------------------------------------------------
__global__ void reduce_kernel(float* __restrict__ out) {
    __shared__ float4 tile[32][33];
    const int b0 = blockIdx.x * 32;
    const int tx = threadIdx.x, ty = threadIdx.y;   // (32, 8)
    const size_t cstride = (size_t)B_DIM * (O_DIM / 4);

    const float4* pbase = (const float4*)&g_partial[0][0][0];
#pragma unroll
    for (int r = 0; r < 4; r++) {
        int b = ty + r * 8;
        const float4* p = pbase + (size_t)(b0 + b) * (O_DIM / 4) + tx;
        float4 s = p[0];
#pragma unroll
        for (int c = 1; c < C_CHUNKS; c++) {
            float4 v = p[c * cstride];
            s.x += v.x; s.y += v.y; s.z += v.z; s.w += v.w;
        }
        tile[b][tx] = s;
    }
    __syncthreads();

    const float* tf = (const float*)tile;   // row stride = 132 floats
#pragma unroll
    for (int r = 0; r < 16; r++) {
        int o = ty + r * 8;
        out[(size_t)o * B_DIM + b0 + tx] = tf[tx * 132 + o];
    }
}

// ---------------------------------------------------------------------------
extern "C" void kernel_launch(void* const* d_in, const int* in_sizes, int n_in,
                              void* d_out, int out_size) {
    const float* x       = (const float*)d_in[0];   // [128, 8192]
    const float* P       = (const float*)d_in[1];   // [129, 128, 128]
    const float* borders = (const float*)d_in[2];   // [129]
    const float* invl    = (const float*)d_in[3];   // [128]
    float*       out     = (float*)d_out;           // [128, 8192]

    cudaFuncSetAttribute(main_kernel,
                         cudaFuncAttributeMaxDynamicSharedMemorySize, SMEM_MAIN);

    transpose_kernel<<<dim3(4, G1), 128>>>(P);
    main_kernel<<<dim3(NBT, C_CHUNKS), THREADS, SMEM_MAIN>>>(x, borders, invl);
    reduce_kernel<<<B_DIM / 32, dim3(32, 8)>>>(out);
}

// round 8
// speedup vs baseline: 1.2240x; 1.2240x over previous
#include <cuda_runtime.h>
#include <cuda_fp16.h>

#define I_DIM   128
#define O_DIM   128
#define G_NUM   128
#define G1      129
#define B_DIM   8192
#define C_CHUNKS 4
#define ICHUNK  (I_DIM / C_CHUNKS)   /* 32 */
#define BT      256                  /* batch columns per block */
#define NBT     (B_DIM / BT)         /* 32 */
#define THREADS 512
#define NWARP   (THREADS / 32)       /* 16 */
#define BPW     (BT / NWARP)         /* 16 batch columns per warp */
#define ROW_U4  (O_DIM / 8)          /* 16 uint4 per 256B fp16 row */

// Static device scratch (allocation-free per harness rules)
__device__ __align__(256) __half g_P2h[(size_t)I_DIM * G1 * O_DIM]; // [i][g][o] 4.2MB
__device__ float g_partial[C_CHUNKS][B_DIM][O_DIM];                 // [c][b][o] 16MB

// ---------------------------------------------------------------------------
// Kernel 1 (PROVEN round-4): transpose+quantize P[g][o][i] -> P2h[i][g][o].
// Block = (one g, 32 i's), 128 threads. LDG.128 reads, conflict-free STS,
// half2 coalesced writes.
// ---------------------------------------------------------------------------
__global__ void transpose_kernel(const float* __restrict__ P) {
    __shared__ float tile[O_DIM][33];
    const int g  = blockIdx.y;           // 0..128
    const int i0 = blockIdx.x * 32;      // 0..96
    const int t = threadIdx.x, w = t >> 5, lane = t & 31;
    const int quad = lane >> 3;          // 0..3
    const int sub  = lane & 7;           // 0..7

    const float4* src = (const float4*)(P + (size_t)g * O_DIM * I_DIM + i0);
    float4 v[8];
#pragma unroll
    for (int r = 0; r < 8; r++) {
        int o = w * 32 + r * 4 + quad;
        v[r] = src[(size_t)o * (I_DIM / 4) + sub];
    }
#pragma unroll
    for (int r = 0; r < 8; r++) {
        int o = w * 32 + r * 4 + quad;
        tile[o][sub * 4 + 0] = v[r].x;
        tile[o][sub * 4 + 1] = v[r].y;
        tile[o][sub * 4 + 2] = v[r].z;
        tile[o][sub * 4 + 3] = v[r].w;
    }
    __syncthreads();

    const int op = t & 63;          // o-pair index
    const int il = t >> 6;          // 0..1
    __half2* dst = (__half2*)g_P2h;
#pragma unroll
    for (int r = 0; r < 16; r++) {
        int i = il + 2 * r;         // 0..31 (in tile bounds)
        dst[((size_t)(i0 + i) * G1 + g) * (O_DIM / 2) + op] =
            __floats2half2_rn(tile[2 * op][i], tile[2 * op + 1][i]);
    }
}

// ---------------------------------------------------------------------------
// Kernel 2: gather + lerp (half2). Block = 256 b x 32 i.
// NEW layout: lane = (lq2, le): lq2 selects the column of a pair, le the
// 16B chunk (8 outputs). One LDG.128 per (col, row) -> half the LDG issue
// count of round 4 at identical mandatory wavefronts.
// ---------------------------------------------------------------------------
__global__ __launch_bounds__(THREADS, 1)
void main_kernel(const float* __restrict__ x,
                 const float* __restrict__ borders,
                 const float* __restrict__ invl) {
    __shared__ __align__(16) unsigned s_gd[ICHUNK][BT];   // 32 KB
    __shared__ float s_b[G1];
    __shared__ float s_il[G_NUM];

    const int t     = threadIdx.x;
    const int btile = blockIdx.x;    // 0..31
    const int chunk = blockIdx.y;    // 0..3
    const int b0    = btile * BT;
    const int i0    = chunk * ICHUNK;

    if (t < G1)    s_b[t]  = borders[t];
    if (t < G_NUM) s_il[t] = invl[t];
    __syncthreads();

    // Phase 1: bucket index g + weight d, packed (g | half(d)<<16)
    {
        const int bl    = t & (BT - 1);
        const int ibase = t >> 8;
#pragma unroll
        for (int p = 0; p < ICHUNK / 2; p++) {
            int il = ibase + 2 * p;
            float xv = x[(size_t)(i0 + il) * B_DIM + b0 + bl];
            float e  = __expf(-fabsf(xv));
            float cdf = (xv > 0.f) ? (1.f - 0.5f * e) : (0.5f * e);
            int g = (int)(cdf * (float)G_NUM);
            g = min(max(g, 0), G_NUM - 1);
            float d = (xv - s_b[g]) * s_il[g];
            unsigned db = (unsigned)__half_as_ushort(__float2half_rn(d));
            s_gd[il][bl] = (unsigned)g | (db << 16);
        }
    }
    __syncthreads();

    const int w    = t >> 5;
    const int lane = t & 31;
    const int wb   = w * BPW;        // 16 batch cols per warp
    const int lq2  = lane >> 4;      // 0..1 : column within a pair
    const int le   = lane & 15;      // 16B chunk (8 outputs) within 256B row

    const __half2 one2 = __floats2half2_rn(1.f, 1.f);
    const __half2 z2   = __floats2half2_rn(0.f, 0.f);
    const uint4* __restrict__ P2v = (const uint4*)g_P2h;

    float4 accA[8], accB[8];
#pragma unroll
    for (int jp = 0; jp < 8; jp++) {
        accA[jp] = make_float4(0.f, 0.f, 0.f, 0.f);
        accB[jp] = make_float4(0.f, 0.f, 0.f, 0.f);
    }

    for (int iiB = 0; iiB < ICHUNK; iiB += 4) {
        __half2 h0[8], h1[8], h2[8], h3[8];
#pragma unroll
        for (int jp = 0; jp < 8; jp++) { h0[jp] = z2; h1[jp] = z2; h2[jp] = z2; h3[jp] = z2; }

#pragma unroll
        for (int u = 0; u < 4; u++) {
            const int ii = iiB + u;
            const uint4* slice = P2v + (size_t)(i0 + ii) * (G1 * ROW_U4);
#pragma unroll
            for (int jp = 0; jp < 8; jp++) {
                // lanes 0-15 take col wb+2jp, lanes 16-31 take wb+2jp+1
                unsigned v  = s_gd[ii][wb + 2 * jp + lq2];
                unsigned gi = v & 0xFFu;
                unsigned dd = __byte_perm(v, v, 0x3232);
                __half2 d2  = *(__half2*)&dd;
                __half2 w2  = __hsub2(one2, d2);
                const uint4* base = slice + gi * ROW_U4;
                uint4 A  = __ldg(base + le);            // row g   (LDG.128)
                uint4 Bv = __ldg(base + ROW_U4 + le);   // row g+1 (adjacent)
                h0[jp] = __hfma2(d2, *(__half2*)&Bv.x, __hfma2(w2, *(__half2*)&A.x, h0[jp]));
                h1[jp] = __hfma2(d2, *(__half2*)&Bv.y, __hfma2(w2, *(__half2*)&A.y, h1[jp]));
                h2[jp] = __hfma2(d2, *(__half2*)&Bv.z, __hfma2(w2, *(__half2*)&A.z, h2[jp]));
                h3[jp] = __hfma2(d2, *(__half2*)&Bv.w, __hfma2(w2, *(__half2*)&A.w, h3[jp]));
            }
        }

        // flush half2 partials into fp32 accumulators every 4 slices
#pragma unroll
        for (int jp = 0; jp < 8; jp++) {
            float2 p0 = __half22float2(h0[jp]);
            float2 p1 = __half22float2(h1[jp]);
            float2 p2 = __half22float2(h2[jp]);
            float2 p3 = __half22float2(h3[jp]);
            accA[jp].x += p0.x; accA[jp].y += p0.y;
            accA[jp].z += p1.x; accA[jp].w += p1.y;
            accB[jp].x += p2.x; accB[jp].y += p2.y;
            accB[jp].z += p3.x; accB[jp].w += p3.y;
        }
        // keep all 16 warps on the same ~132KB 4-slice window (L1 reuse)
        __syncthreads();
    }

    // Store: lane covers o = le*8 .. le*8+7 for its 8 columns.
#pragma unroll
    for (int jp = 0; jp < 8; jp++) {
        int b = b0 + wb + 2 * jp + lq2;
        float4* dst = (float4*)&g_partial[chunk][b][le * 8];
        dst[0] = accA[jp];
        dst[1] = accB[jp];
    }
}

// ---------------------------------------------------------------------------
// Kernel 3 (PROVEN round-4): sum partials, transpose [b][o] -> out[o][b].
// ---------------------------------------------------------------------------
__global__ void reduce_kernel(float* __restrict__ out) {
    __shared__ float4 tile[32][33];
    const int b0 = blockIdx.x * 32;
    const int tx = threadIdx.x, ty = threadIdx.y;   // (32, 8)
    const size_t cstride = (size_t)B_DIM * (O_DIM / 4);

    const float4* pbase = (const float4*)&g_partial[0][0][0];
#pragma unroll
    for (int r = 0; r < 4; r++) {
        int b = ty + r * 8;
        const float4* p = pbase + (size_t)(b0 + b) * (O_DIM / 4) + tx;
        float4 s = p[0];
#pragma unroll
        for (int c = 1; c < C_CHUNKS; c++) {
            float4 v = p[c * cstride];
            s.x += v.x; s.y += v.y; s.z += v.z; s.w += v.w;
        }
        tile[b][tx] = s;
    }
    __syncthreads();

    const float* tf = (const float*)tile;   // row stride = 132 floats
#pragma unroll
    for (int r = 0; r < 16; r++) {
        int o = ty + r * 8;
        out[(size_t)o * B_DIM + b0 + tx] = tf[tx * 132 + o];
    }
}

// ---------------------------------------------------------------------------
extern "C" void kernel_launch(void* const* d_in, const int* in_sizes, int n_in,
                              void* d_out, int out_size) {
    const float* x       = (const float*)d_in[0];   // [128, 8192]
    const float* P       = (const float*)d_in[1];   // [129, 128, 128]
    const float* borders = (const float*)d_in[2];   // [129]
    const float* invl    = (const float*)d_in[3];   // [128]
    float*       out     = (float*)d_out;           // [128, 8192]

    transpose_kernel<<<dim3(4, G1), 128>>>(P);
    main_kernel<<<dim3(NBT, C_CHUNKS), THREADS>>>(x, borders, invl);
    reduce_kernel<<<B_DIM / 32, dim3(32, 8)>>>(out);
}

// round 9
// speedup vs baseline: 1.2826x; 1.0478x over previous
#include <cuda_runtime.h>
#include <cuda_fp16.h>

#define I_DIM   128
#define O_DIM   128
#define G_NUM   128
#define G1      129
#define B_DIM   8192
#define C_CHUNKS 4
#define ICHUNK  (I_DIM / C_CHUNKS)   /* 32 */
#define BT      256                  /* batch columns per block */
#define NBT     (B_DIM / BT)         /* 32 */
#define THREADS 512
#define NWARP   (THREADS / 32)       /* 16 */
#define BPW     (BT / NWARP)         /* 16 batch columns per warp */
#define ROW_U2  (O_DIM / 4)          /* 32 uint2 per 256B fp16 row */

// Static device scratch (allocation-free per harness rules)
__device__ __align__(256) __half g_P2h[(size_t)I_DIM * G1 * O_DIM]; // [i][g][o] 4.2MB
__device__ float g_partial[C_CHUNKS][B_DIM][O_DIM];                 // [c][b][o] 16MB

// ---------------------------------------------------------------------------
// Kernel 1: transpose+quantize P[g][o][i] -> P2h[i][g][o].
// 256-thread blocks handle TWO g's (gg = w>>2) with the proven round-4
// quad/sub conflict-free pattern per g. Grid (4 i-tiles, 65 g-pairs),
// guard g < 129. 6 blocks/SM co-resident -> latency hidden.
// ---------------------------------------------------------------------------
__global__ __launch_bounds__(256, 1)
void transpose_kernel(const float* __restrict__ P) {
    __shared__ float tile[2][O_DIM][33];
    const int g0 = blockIdx.y * 2;       // 0,2,...,128
    const int i0 = blockIdx.x * 32;      // 0..96
    const int t = threadIdx.x;
    const int w = t >> 5, lane = t & 31;
    const int gg = w >> 2;               // 0..1: which g this warp serves
    const int w2 = w & 3;                // 0..3: warp within the g
    const int quad = lane >> 3;          // 0..3
    const int sub  = lane & 7;           // 0..7
    const int g = g0 + gg;

    if (g <= G_NUM) {
        const float4* src = (const float4*)(P + (size_t)g * O_DIM * I_DIM + i0);
        float4 v[8];
#pragma unroll
        for (int r = 0; r < 8; r++) {
            int o = w2 * 32 + r * 4 + quad;
            v[r] = src[(size_t)o * (I_DIM / 4) + sub];
        }
#pragma unroll
        for (int r = 0; r < 8; r++) {
            int o = w2 * 32 + r * 4 + quad;
            tile[gg][o][sub * 4 + 0] = v[r].x;
            tile[gg][o][sub * 4 + 1] = v[r].y;
            tile[gg][o][sub * 4 + 2] = v[r].z;
            tile[gg][o][sub * 4 + 3] = v[r].w;
        }
    }
    __syncthreads();

    const int op  = t & 63;          // o-pair index 0..63
    const int il  = (t >> 6) & 1;    // 0..1
    const int gg2 = t >> 7;          // 0..1
    const int gs  = g0 + gg2;
    if (gs <= G_NUM) {
        __half2* dst = (__half2*)g_P2h;
#pragma unroll
        for (int r = 0; r < 16; r++) {
            int i = il + 2 * r;          // 0..31
            dst[((size_t)(i0 + i) * G1 + gs) * (O_DIM / 2) + op] =
                __floats2half2_rn(tile[gg2][2 * op][i], tile[gg2][2 * op + 1][i]);
        }
    }
}

// ---------------------------------------------------------------------------
// Kernel 2 (round-4 gather, PROVEN fastest): Block = 256 b x 32 i.
// Warp handles 16 batch cols; lane covers 4 outputs (uint2).
// Barrier thinned to every 8 slices: warps drift/pipeline across slice
// boundaries instead of stalling together on cold L2 hits.
// ---------------------------------------------------------------------------
__global__ __launch_bounds__(THREADS, 1)
void main_kernel(const float* __restrict__ x,
                 const float* __restrict__ borders,
                 const float* __restrict__ invl) {
    __shared__ __align__(16) unsigned s_gd[ICHUNK][BT];   // 32 KB
    __shared__ float s_b[G1];
    __shared__ float s_il[G_NUM];

    const int t     = threadIdx.x;
    const int btile = blockIdx.x;    // 0..31
    const int chunk = blockIdx.y;    // 0..3
    const int b0    = btile * BT;
    const int i0    = chunk * ICHUNK;

    if (t < G1)    s_b[t]  = borders[t];
    if (t < G_NUM) s_il[t] = invl[t];
    __syncthreads();

    // Phase 1: bucket index g + weight d, packed (g | half(d)<<16)
    {
        const int bl    = t & (BT - 1);
        const int ibase = t >> 8;
#pragma unroll
        for (int p = 0; p < ICHUNK / 2; p++) {
            int il = ibase + 2 * p;
            float xv = x[(size_t)(i0 + il) * B_DIM + b0 + bl];
            float e  = __expf(-fabsf(xv));
            float cdf = (xv > 0.f) ? (1.f - 0.5f * e) : (0.5f * e);
            int g = (int)(cdf * (float)G_NUM);
            g = min(max(g, 0), G_NUM - 1);
            float d = (xv - s_b[g]) * s_il[g];
            unsigned db = (unsigned)__half_as_ushort(__float2half_rn(d));
            s_gd[il][bl] = (unsigned)g | (db << 16);
        }
    }
    __syncthreads();

    const int w    = t >> 5;
    const int lane = t & 31;
    const int wb   = w * BPW;

    const __half2 one2 = __floats2half2_rn(1.f, 1.f);
    const __half2 z2   = __floats2half2_rn(0.f, 0.f);
    const uint2* __restrict__ P2v = (const uint2*)g_P2h;

    float4 accF[BPW];
#pragma unroll
    for (int j = 0; j < BPW; j++) accF[j] = make_float4(0.f, 0.f, 0.f, 0.f);

    for (int iiB = 0; iiB < ICHUNK; iiB += 4) {
        __half2 a0[BPW], a1[BPW];
#pragma unroll
        for (int j = 0; j < BPW; j++) { a0[j] = z2; a1[j] = z2; }

#pragma unroll
        for (int u = 0; u < 4; u++) {
            const int ii = iiB + u;
            const uint2* slice = P2v + (size_t)(i0 + ii) * (G1 * ROW_U2);
#pragma unroll
            for (int j = 0; j < BPW; j++) {
                unsigned v  = s_gd[ii][wb + j];     // broadcast LDS
                unsigned gi = v & 0xFFu;
                unsigned dd = __byte_perm(v, v, 0x3232);
                __half2 d2  = *(__half2*)&dd;
                __half2 w2  = __hsub2(one2, d2);
                const uint2* rowp = slice + gi * ROW_U2 + lane;
                uint2 A  = __ldg(rowp);             // row g   (256B coalesced)
                uint2 Bv = __ldg(rowp + ROW_U2);    // row g+1 (adjacent)
                a0[j] = __hfma2(w2, *(__half2*)&A.x,  a0[j]);
                a0[j] = __hfma2(d2, *(__half2*)&Bv.x, a0[j]);
                a1[j] = __hfma2(w2, *(__half2*)&A.y,  a1[j]);
                a1[j] = __hfma2(d2, *(__half2*)&Bv.y, a1[j]);
            }
        }

        // flush half2 partials into fp32 accumulators every 4 slices
#pragma unroll
        for (int j = 0; j < BPW; j++) {
            float2 p0 = __half22float2(a0[j]);
            float2 p1 = __half22float2(a1[j]);
            accF[j].x += p0.x; accF[j].y += p0.y;
            accF[j].z += p1.x; accF[j].w += p1.y;
        }
        // Thinned barrier: re-converge warps every 8 slices only.
        if (iiB & 4) __syncthreads();
    }

    // Coalesced float4 stores into [c][b][o] scratch.
#pragma unroll
    for (int j = 0; j < BPW; j++) {
        float4* dst = (float4*)&g_partial[chunk][b0 + wb + j][0];
        dst[lane] = accF[j];
    }
}

// ---------------------------------------------------------------------------
// Kernel 3 (PROVEN): sum partials, transpose [b][o] -> out[o][b].
// ---------------------------------------------------------------------------
__global__ void reduce_kernel(float* __restrict__ out) {
    __shared__ float4 tile[32][33];
    const int b0 = blockIdx.x * 32;
    const int tx = threadIdx.x, ty = threadIdx.y;   // (32, 8)
    const size_t cstride = (size_t)B_DIM * (O_DIM / 4);

    const float4* pbase = (const float4*)&g_partial[0][0][0];
#pragma unroll
    for (int r = 0; r < 4; r++) {
        int b = ty + r * 8;
        const float4* p = pbase + (size_t)(b0 + b) * (O_DIM / 4) + tx;
        float4 s = p[0];
#pragma unroll
        for (int c = 1; c < C_CHUNKS; c++) {
            float4 v = p[c * cstride];
            s.x += v.x; s.y += v.y; s.z += v.z; s.w += v.w;
        }
        tile[b][tx] = s;
    }
    __syncthreads();

    const float* tf = (const float*)tile;   // row stride = 132 floats
#pragma unroll
    for (int r = 0; r < 16; r++) {
        int o = ty + r * 8;
        out[(size_t)o * B_DIM + b0 + tx] = tf[tx * 132 + o];
    }
}

// ---------------------------------------------------------------------------
extern "C" void kernel_launch(void* const* d_in, const int* in_sizes, int n_in,
                              void* d_out, int out_size) {
    const float* x       = (const float*)d_in[0];   // [128, 8192]
    const float* P       = (const float*)d_in[1];   // [129, 128, 128]
    const float* borders = (const float*)d_in[2];   // [129]
    const float* invl    = (const float*)d_in[3];   // [128]
    float*       out     = (float*)d_out;           // [128, 8192]

    transpose_kernel<<<dim3(4, 65), 256>>>(P);
    main_kernel<<<dim3(NBT, C_CHUNKS), THREADS>>>(x, borders, invl);
    reduce_kernel<<<B_DIM / 32, dim3(32, 8)>>>(out);
}